// round 9
// baseline (speedup 1.0000x reference)
#include <cuda_runtime.h>
#include <cuda_bf16.h>
#include <cfloat>
#include <math.h>
#include <cstdint>

#define BSZ 8
#define P1  8192
#define P2  2048
#define KNB 32
#define NQ  16384
#define NTOT 524288ull

typedef unsigned long long ull;

__device__ int    g_nn[NQ*KNB];
__device__ float  g_bufA[NTOT*64];    // y1 [n][64]
__device__ float  g_bufB[NTOT*64];    // y2 [n][64]
__device__ float  g_mx[NQ*128];
__device__ float  g_mn[NQ*128];
__device__ double g_sum[128];
__device__ double g_sqsum[128];
__device__ float  g_scale[3][128];
__device__ float  g_shift[3][128];

static __device__ __forceinline__ uint32_t smem_u32(const void* p) {
    uint32_t a; asm("{ .reg .u64 t; cvta.to.shared.u64 t, %1; cvt.u32.u64 %0, t; }" : "=r"(a) : "l"(p));
    return a;
}
static __device__ __forceinline__ void ldsm4(uint32_t* r, uint32_t a) {
    asm volatile("ldmatrix.sync.aligned.m8n8.x4.shared.b16 {%0,%1,%2,%3}, [%4];"
        : "=r"(r[0]), "=r"(r[1]), "=r"(r[2]), "=r"(r[3]) : "r"(a));
}
static __device__ __forceinline__ void ldsm2(uint32_t* r, uint32_t a) {
    asm volatile("ldmatrix.sync.aligned.m8n8.x2.shared.b16 {%0,%1}, [%2];"
        : "=r"(r[0]), "=r"(r[1]) : "r"(a));
}
static __device__ __forceinline__ void mma16816(float* d, const uint32_t* a, const uint32_t* b) {
    asm volatile("mma.sync.aligned.m16n8k16.row.col.f32.bf16.bf16.f32 "
        "{%0,%1,%2,%3},{%4,%5,%6,%7},{%8,%9},{%0,%1,%2,%3};"
        : "+f"(d[0]), "+f"(d[1]), "+f"(d[2]), "+f"(d[3])
        : "r"(a[0]), "r"(a[1]), "r"(a[2]), "r"(a[3]), "r"(b[0]), "r"(b[1]));
}
static __device__ __forceinline__ void split1(float v, __nv_bfloat16 &h, __nv_bfloat16 &l) {
    h = __float2bfloat16_rn(v);
    l = __float2bfloat16_rn(v - __bfloat162float(h));
}
static __device__ __forceinline__ void split4(float4 v, uint2 &H, uint2 &L) {
    __nv_bfloat16 hx, hy, hz, hw, lx, ly, lz, lw;
    split1(v.x, hx, lx); split1(v.y, hy, ly);
    split1(v.z, hz, lz); split1(v.w, hw, lw);
    H.x = (uint32_t)__bfloat16_as_ushort(hx) | ((uint32_t)__bfloat16_as_ushort(hy) << 16);
    H.y = (uint32_t)__bfloat16_as_ushort(hz) | ((uint32_t)__bfloat16_as_ushort(hw) << 16);
    L.x = (uint32_t)__bfloat16_as_ushort(lx) | ((uint32_t)__bfloat16_as_ushort(ly) << 16);
    L.y = (uint32_t)__bfloat16_as_ushort(lz) | ((uint32_t)__bfloat16_as_ushort(lw) << 16);
}

// lexicographic (d, i) bitonic merge of own sorted list with smem list (read at 31-lane)
static __device__ __forceinline__ void merge32(float &d, int &i, const float* sd, const int* si, int lane) {
    float bd = sd[31 - lane];
    int   bi = si[31 - lane];
    bool takeA = (d < bd) || (d == bd && i < bi);
    float md = takeA ? d : bd;
    int   mi = takeA ? i : bi;
    #pragma unroll
    for (int off = 16; off; off >>= 1) {
        float pd = __shfl_xor_sync(0xffffffffu, md, off);
        int   pi = __shfl_xor_sync(0xffffffffu, mi, off);
        bool lower = (lane & off) == 0;
        bool pless = (pd < md) || (pd == md && pi < mi);
        if (lower == pless) { md = pd; mi = pi; }
    }
    d = md; i = mi;
}

// -------- KNN: 4 warps per query (2048 pts each) + bitonic merges --------
__global__ __launch_bounds__(1024) void knn_kernel(const float* __restrict__ xyz,
                           const int*   __restrict__ sidx,
                           float*       __restrict__ out_xyz) {
    extern __shared__ char knnsm[];
    float4* pts = (float4*)knnsm;                     // 8192*16B = 128KB
    float*  sd  = (float*)(knnsm + 131072);           // [32][32] dists
    int*    si  = (int*)(knnsm + 131072 + 4096);      // [32][32] idx
    const int tid  = threadIdx.x;
    const int w    = tid >> 5, lane = tid & 31;
    const int qbase = blockIdx.x * 8;                 // 8 queries per block
    const int b = qbase / P2;
    const float* bx = xyz + (size_t)b * P1 * 3;

    for (int j = tid; j < P1; j += 1024) {
        float x = bx[3*j], y = bx[3*j+1], z = bx[3*j+2];
        float r2 = __fadd_rn(__fadd_rn(__fmul_rn(x,x), __fmul_rn(y,y)), __fmul_rn(z,z));
        pts[j] = make_float4(x, y, z, r2);
    }
    __syncthreads();

    const int qg   = w >> 2;           // query within block
    const int quad = w & 3;            // point quarter
    const int q    = qbase + qg;
    const int si_  = sidx[q];
    const float qx = bx[3*si_], qy = bx[3*si_+1], qz = bx[3*si_+2];
    const float rA = __fadd_rn(__fadd_rn(__fmul_rn(qx,qx), __fmul_rn(qy,qy)), __fmul_rn(qz,qz));
    if (quad == 0 && lane < 3)
        out_xyz[(size_t)q*3 + lane] = (lane == 0) ? qx : (lane == 1 ? qy : qz);

    float best_d = FLT_MAX; int best_i = 0;   // ascending across lanes
    float thr = FLT_MAX;
    const int p0 = quad * 2048;

    for (int j0 = 0; j0 < 2048; j0 += 32) {
        float4 pt = pts[p0 + j0 + lane];
        float dot = __fmaf_rn(qz, pt.z, __fmaf_rn(qy, pt.y, __fmul_rn(qx, pt.x)));
        float d   = __fadd_rn(__fsub_rn(rA, __fmul_rn(2.f, dot)), pt.w);
        unsigned m = __ballot_sync(0xffffffffu, d < thr);
        while (m) {
            int src = __ffs(m) - 1; m &= m - 1;
            float dc = __shfl_sync(0xffffffffu, d, src);
            unsigned bal = __ballot_sync(0xffffffffu, dc < best_d);
            if (bal) {
                int pos  = __ffs(bal) - 1;
                float ud = __shfl_up_sync(0xffffffffu, best_d, 1);
                int   ui = __shfl_up_sync(0xffffffffu, best_i, 1);
                if (lane > pos)       { best_d = ud; best_i = ui; }
                else if (lane == pos) { best_d = dc; best_i = p0 + j0 + src; }
            }
        }
        thr = __shfl_sync(0xffffffffu, best_d, 31);
    }
    sd[w*32 + lane] = best_d;
    si[w*32 + lane] = best_i;
    __syncthreads();

    // stage A: 16 warps merge pairs (4g+2p, 4g+2p+1) -> slot 4g+2p
    if (w < 16) {
        int g = w >> 1, p = w & 1;
        int l0 = 4*g + 2*p;
        float d = sd[l0*32 + lane]; int i = si[l0*32 + lane];
        merge32(d, i, sd + (l0+1)*32, si + (l0+1)*32, lane);
        sd[l0*32 + lane] = d; si[l0*32 + lane] = i;
    }
    __syncthreads();

    // stage B: 8 warps merge (4g, 4g+2) -> final
    if (w < 8) {
        float d = sd[4*w*32 + lane]; int i = si[4*w*32 + lane];
        merge32(d, i, sd + (4*w+2)*32, si + (4*w+2)*32, lane);
        g_nn[(size_t)(qbase + w)*KNB + lane] = i;
    }
}

// -------- GEMM layer via mma.sync bf16 (3-term split), M=128/CTA --------
// Epilogue fuses BN stats (always) and, for POOL=1, per-query max/min (no y write).
template<int KPAD, int CIN, int N, int MODE, int POOL>
__global__ __launch_bounds__(256) void gemm_kernel(
        const float* __restrict__ feat, const float* __restrict__ xyz,
        const float* __restrict__ qxyz, const float* __restrict__ y_in,
        const float* __restrict__ W,    float* __restrict__ y_out, int prev)
{
    extern __shared__ char smem[];
    constexpr int ST = KPAD + 8;
    constexpr int OFF_AH = 0;
    constexpr int OFF_AL = 128*ST*2;
    constexpr int OFF_BH = 2*OFF_AL;
    constexpr int OFF_BL = OFF_BH + N*ST*2;
    constexpr int OFF_S  = OFF_BL + N*ST*2;     // float ssum[N], ssq[N]
    float* ssum = (float*)(smem + OFF_S);
    float* ssq  = ssum + N;
    const uint32_t sb = smem_u32(smem);
    const int tid = threadIdx.x;
    const int n0  = blockIdx.x * 128;
    const int cq  = tid & 15, rs = tid >> 4;

    if (tid < N) { ssum[tid] = 0.f; ssq[tid] = 0.f; }

    if (MODE == 0) {
        uint4 z = make_uint4(0,0,0,0);
        if (tid < 128 + N) {
            int isA = tid < 128;
            int row = isA ? tid : tid - 128;
            char* base = smem + (isA ? OFF_AH : OFF_BH) + row*ST*2 + 128;
            char* basl = smem + (isA ? OFF_AL : OFF_BL) + row*ST*2 + 128;
            *(uint4*)(base) = z;      *(uint4*)(base + 16) = z;
            *(uint4*)(basl) = z;      *(uint4*)(basl + 16) = z;
        }
        #pragma unroll
        for (int it = 0; it < 8; it++) {
            int row = rs + 16*it;
            int n   = n0 + row;
            int b   = n >> 16;
            int nn  = g_nn[n];
            float4 f = *(const float4*)(feat + (size_t)(b*P1 + nn)*64 + 4*cq);
            uint2 H, L; split4(f, H, L);
            *(uint2*)(smem + OFF_AH + row*ST*2 + 8*cq) = H;
            *(uint2*)(smem + OFF_AL + row*ST*2 + 8*cq) = L;
            if (cq == 0) {
                int q = n >> 5;
                const float* nx = xyz  + (size_t)(b*P1 + nn)*3;
                const float* qp = qxyz + (size_t)q*3;
                #pragma unroll
                for (int j = 0; j < 3; j++) {
                    __nv_bfloat16 h, l; split1(__fsub_rn(nx[j], qp[j]), h, l);
                    *(__nv_bfloat16*)(smem + OFF_AH + row*ST*2 + 128 + 2*j) = h;
                    *(__nv_bfloat16*)(smem + OFF_AL + row*ST*2 + 128 + 2*j) = l;
                }
            }
        }
        #pragma unroll
        for (int it = 0; it < N/16; it++) {
            int o = rs + 16*it;
            const float* wr = W + (size_t)o*CIN;
            float4 w4 = make_float4(wr[4*cq], wr[4*cq+1], wr[4*cq+2], wr[4*cq+3]);
            uint2 H, L; split4(w4, H, L);
            *(uint2*)(smem + OFF_BH + o*ST*2 + 8*cq) = H;
            *(uint2*)(smem + OFF_BL + o*ST*2 + 8*cq) = L;
            if (cq == 0) {
                #pragma unroll
                for (int j = 0; j < 3; j++) {
                    __nv_bfloat16 h, l; split1(wr[64 + j], h, l);
                    *(__nv_bfloat16*)(smem + OFF_BH + o*ST*2 + 128 + 2*j) = h;
                    *(__nv_bfloat16*)(smem + OFF_BL + o*ST*2 + 128 + 2*j) = l;
                }
            }
        }
    } else {
        const float4 sc4 = *(const float4*)(g_scale[prev] + 4*cq);
        const float4 sh4 = *(const float4*)(g_shift[prev] + 4*cq);
        #pragma unroll
        for (int it = 0; it < 8; it++) {
            int row = rs + 16*it;
            float4 v = *(const float4*)(y_in + (size_t)(n0 + row)*64 + 4*cq);
            v.x = fmaxf(__fmaf_rn(sc4.x, v.x, sh4.x), 0.f);
            v.y = fmaxf(__fmaf_rn(sc4.y, v.y, sh4.y), 0.f);
            v.z = fmaxf(__fmaf_rn(sc4.z, v.z, sh4.z), 0.f);
            v.w = fmaxf(__fmaf_rn(sc4.w, v.w, sh4.w), 0.f);
            uint2 H, L; split4(v, H, L);
            *(uint2*)(smem + OFF_AH + row*ST*2 + 8*cq) = H;
            *(uint2*)(smem + OFF_AL + row*ST*2 + 8*cq) = L;
        }
        #pragma unroll
        for (int it = 0; it < N/16; it++) {
            int o = rs + 16*it;
            float4 w4 = *(const float4*)(W + (size_t)o*64 + 4*cq);
            uint2 H, L; split4(w4, H, L);
            *(uint2*)(smem + OFF_BH + o*ST*2 + 8*cq) = H;
            *(uint2*)(smem + OFF_BL + o*ST*2 + 8*cq) = L;
        }
    }
    __syncthreads();

    const int w = tid >> 5, lane = tid & 31;
    const int mw = w & 3, nw = w >> 2;          // warp: rows mw*32..+31 (one query), cols nw*(N/2)
    constexpr int NB = N/16;

    float acc[2][NB][4];
    #pragma unroll
    for (int mh = 0; mh < 2; mh++)
        #pragma unroll
        for (int nb = 0; nb < NB; nb++)
            #pragma unroll
            for (int j = 0; j < 4; j++) acc[mh][nb][j] = 0.f;

    const uint32_t aoff = ((mw*32 + (lane & 15))*ST + (lane >> 4)*8) * 2;
    const uint32_t boff = ((nw*(N/2) + (lane & 7))*ST + ((lane >> 3) & 1)*8) * 2;

    #pragma unroll
    for (int kk = 0; kk < KPAD/16; kk++) {
        uint32_t ah[2][4], al[2][4];
        #pragma unroll
        for (int mh = 0; mh < 2; mh++) {
            ldsm4(ah[mh], sb + OFF_AH + aoff + (mh*16*ST + kk*16)*2);
            ldsm4(al[mh], sb + OFF_AL + aoff + (mh*16*ST + kk*16)*2);
        }
        #pragma unroll
        for (int nb = 0; nb < NB; nb++) {
            uint32_t bh[2], bl[2];
            ldsm2(bh, sb + OFF_BH + boff + (nb*8*ST + kk*16)*2);
            ldsm2(bl, sb + OFF_BL + boff + (nb*8*ST + kk*16)*2);
            #pragma unroll
            for (int mh = 0; mh < 2; mh++) {
                mma16816(acc[mh][nb], ah[mh], bh);
                mma16816(acc[mh][nb], ah[mh], bl);
                mma16816(acc[mh][nb], al[mh], bh);
            }
        }
    }

    const int g = lane >> 2, t = lane & 3;
    #pragma unroll
    for (int nb = 0; nb < NB; nb++) {
        float s0 = acc[0][nb][0] + acc[0][nb][2] + acc[1][nb][0] + acc[1][nb][2];
        float s1 = acc[0][nb][1] + acc[0][nb][3] + acc[1][nb][1] + acc[1][nb][3];
        float q0 = acc[0][nb][0]*acc[0][nb][0] + acc[0][nb][2]*acc[0][nb][2]
                 + acc[1][nb][0]*acc[1][nb][0] + acc[1][nb][2]*acc[1][nb][2];
        float q1 = acc[0][nb][1]*acc[0][nb][1] + acc[0][nb][3]*acc[0][nb][3]
                 + acc[1][nb][1]*acc[1][nb][1] + acc[1][nb][3]*acc[1][nb][3];
        float mx0, mn0, mx1, mn1;
        if (POOL) {
            mx0 = fmaxf(fmaxf(acc[0][nb][0], acc[0][nb][2]), fmaxf(acc[1][nb][0], acc[1][nb][2]));
            mn0 = fminf(fminf(acc[0][nb][0], acc[0][nb][2]), fminf(acc[1][nb][0], acc[1][nb][2]));
            mx1 = fmaxf(fmaxf(acc[0][nb][1], acc[0][nb][3]), fmaxf(acc[1][nb][1], acc[1][nb][3]));
            mn1 = fminf(fminf(acc[0][nb][1], acc[0][nb][3]), fminf(acc[1][nb][1], acc[1][nb][3]));
        }
        #pragma unroll
        for (int off = 4; off < 32; off <<= 1) {
            s0 += __shfl_xor_sync(0xffffffffu, s0, off);
            s1 += __shfl_xor_sync(0xffffffffu, s1, off);
            q0 += __shfl_xor_sync(0xffffffffu, q0, off);
            q1 += __shfl_xor_sync(0xffffffffu, q1, off);
            if (POOL) {
                mx0 = fmaxf(mx0, __shfl_xor_sync(0xffffffffu, mx0, off));
                mn0 = fminf(mn0, __shfl_xor_sync(0xffffffffu, mn0, off));
                mx1 = fmaxf(mx1, __shfl_xor_sync(0xffffffffu, mx1, off));
                mn1 = fminf(mn1, __shfl_xor_sync(0xffffffffu, mn1, off));
            }
        }
        if (g == 0) {
            int col = nw*(N/2) + nb*8 + 2*t;
            atomicAdd(&ssum[col],   s0); atomicAdd(&ssum[col+1], s1);
            atomicAdd(&ssq[col],    q0); atomicAdd(&ssq[col+1],  q1);
            if (POOL) {
                int q = blockIdx.x*4 + mw;
                g_mx[(size_t)q*128 + col]   = mx0;  g_mn[(size_t)q*128 + col]   = mn0;
                g_mx[(size_t)q*128 + col+1] = mx1;  g_mn[(size_t)q*128 + col+1] = mn1;
            }
        }
    }

    if (!POOL) {
        #pragma unroll
        for (int mh = 0; mh < 2; mh++) {
            #pragma unroll
            for (int nb = 0; nb < NB; nb++) {
                int row = n0 + mw*32 + mh*16 + g;
                int col = nw*(N/2) + nb*8 + 2*t;
                *(float2*)(y_out + (size_t)row*N + col)       = make_float2(acc[mh][nb][0], acc[mh][nb][1]);
                *(float2*)(y_out + (size_t)(row + 8)*N + col) = make_float2(acc[mh][nb][2], acc[mh][nb][3]);
            }
        }
    }

    __syncthreads();
    if (tid < N) {
        atomicAdd(&g_sum[tid],   (double)ssum[tid]);
        atomicAdd(&g_sqsum[tid], (double)ssq[tid]);
    }
}

// -------- BN finalize (bias absorbed by mean subtraction) --------
__global__ void finalize_kernel(const float* __restrict__ gamma,
                                const float* __restrict__ beta,
                                int layer) {
    int o = threadIdx.x;
    double mean = g_sum[o]   * (1.0 / (double)NTOT);
    double var  = g_sqsum[o] * (1.0 / (double)NTOT) - mean*mean;
    float sc = gamma[o] * (float)(1.0 / sqrt(var + 1e-5));
    g_scale[layer][o] = sc;
    g_shift[layer][o] = __fmaf_rn(-(float)mean, sc, beta[o]);
    g_sum[o] = 0.0; g_sqsum[o] = 0.0;
}

// -------- final affine+relu on pooled max/min --------
__global__ void pool_apply_kernel(float* __restrict__ out) {
    int idx = blockIdx.x * 256 + threadIdx.x;
    int o = idx & 127;
    float sc = g_scale[2][o], sh = g_shift[2][o];
    float vmx = __fmaf_rn(sc, g_mx[idx], sh);
    float vmn = __fmaf_rn(sc, g_mn[idx], sh);
    out[idx] = fmaxf(fmaxf(vmx, vmn), 0.f);
}

extern "C" void kernel_launch(void* const* d_in, const int* in_sizes, int n_in,
                              void* d_out, int out_size) {
    const float* xyz  = (const float*)d_in[0];
    const float* feat = (const float*)d_in[1];
    const int*   sidx = (const int*)d_in[2];
    const float *w1=(const float*)d_in[3],
                *g1=(const float*)d_in[5],  *t1=(const float*)d_in[6];
    const float *w2=(const float*)d_in[7],
                *g2=(const float*)d_in[9],  *t2=(const float*)d_in[10];
    const float *w3=(const float*)d_in[11],
                *g3=(const float*)d_in[13], *t3=(const float*)d_in[14];
    float* out      = (float*)d_out;
    float* new_xyz  = out;
    float* new_feat = out + NQ*3;

    float* bufA; cudaGetSymbolAddress((void**)&bufA, g_bufA);
    float* bufB; cudaGetSymbolAddress((void**)&bufB, g_bufB);

    const int SK = 131072 + 8192;                      // pts + merge lists
    const int S1 = (256 + 128) * (80+8) * 2 + 64*8;    // 68096
    const int S2 = (256 + 128) * (64+8) * 2 + 64*8;    // 55808
    const int S3 = (256 + 256) * (64+8) * 2 + 128*8;   // 74752
    cudaFuncSetAttribute(knn_kernel, cudaFuncAttributeMaxDynamicSharedMemorySize, SK);
    cudaFuncSetAttribute(gemm_kernel<80,67,64,0,0>,  cudaFuncAttributeMaxDynamicSharedMemorySize, S1);
    cudaFuncSetAttribute(gemm_kernel<64,64,64,1,0>,  cudaFuncAttributeMaxDynamicSharedMemorySize, S2);
    cudaFuncSetAttribute(gemm_kernel<64,64,128,1,1>, cudaFuncAttributeMaxDynamicSharedMemorySize, S3);

    knn_kernel<<<NQ/8, 1024, SK>>>(xyz, sidx, new_xyz);
    gemm_kernel<80,67,64,0,0><<<NTOT/128, 256, S1>>>(feat, xyz, new_xyz, nullptr, w1, bufA, 0);
    finalize_kernel<<<1,64>>>(g1, t1, 0);
    gemm_kernel<64,64,64,1,0><<<NTOT/128, 256, S2>>>(nullptr, nullptr, nullptr, bufA, w2, bufB, 0);
    finalize_kernel<<<1,64>>>(g2, t2, 1);
    gemm_kernel<64,64,128,1,1><<<NTOT/128, 256, S3>>>(nullptr, nullptr, nullptr, bufB, w3, nullptr, 1);
    finalize_kernel<<<1,128>>>(g3, t3, 2);
    pool_apply_kernel<<<(NQ*128)/256, 256>>>(new_feat);
}

// round 10
// speedup vs baseline: 1.3358x; 1.3358x over previous
#include <cuda_runtime.h>
#include <cuda_bf16.h>
#include <cfloat>
#include <math.h>
#include <cstdint>

#define BSZ 8
#define P1  8192
#define P2  2048
#define KNB 32
#define NQ  16384
#define NTOT 524288ull

typedef unsigned long long ull;

__device__ int    g_nn[NQ*KNB];
__device__ float  g_bufA[NTOT*64];    // y1 [n][64]
__device__ float  g_bufB[NTOT*64];    // y2 [n][64]
__device__ float  g_mx[NQ*128];
__device__ float  g_mn[NQ*128];
__device__ double g_sum[128];
__device__ double g_sqsum[128];
__device__ float  g_scale[3][128];
__device__ float  g_shift[3][128];

static __device__ __forceinline__ uint32_t smem_u32(const void* p) {
    uint32_t a; asm("{ .reg .u64 t; cvta.to.shared.u64 t, %1; cvt.u32.u64 %0, t; }" : "=r"(a) : "l"(p));
    return a;
}
static __device__ __forceinline__ void ldsm4(uint32_t* r, uint32_t a) {
    asm volatile("ldmatrix.sync.aligned.m8n8.x4.shared.b16 {%0,%1,%2,%3}, [%4];"
        : "=r"(r[0]), "=r"(r[1]), "=r"(r[2]), "=r"(r[3]) : "r"(a));
}
static __device__ __forceinline__ void mma16816(float* d, const uint32_t* a, const uint32_t* b) {
    asm volatile("mma.sync.aligned.m16n8k16.row.col.f32.bf16.bf16.f32 "
        "{%0,%1,%2,%3},{%4,%5,%6,%7},{%8,%9},{%0,%1,%2,%3};"
        : "+f"(d[0]), "+f"(d[1]), "+f"(d[2]), "+f"(d[3])
        : "r"(a[0]), "r"(a[1]), "r"(a[2]), "r"(a[3]), "r"(b[0]), "r"(b[1]));
}
static __device__ __forceinline__ void split1(float v, __nv_bfloat16 &h, __nv_bfloat16 &l) {
    h = __float2bfloat16_rn(v);
    l = __float2bfloat16_rn(v - __bfloat162float(h));
}
static __device__ __forceinline__ void split4(float4 v, uint2 &H, uint2 &L) {
    __nv_bfloat16 hx, hy, hz, hw, lx, ly, lz, lw;
    split1(v.x, hx, lx); split1(v.y, hy, ly);
    split1(v.z, hz, lz); split1(v.w, hw, lw);
    H.x = (uint32_t)__bfloat16_as_ushort(hx) | ((uint32_t)__bfloat16_as_ushort(hy) << 16);
    H.y = (uint32_t)__bfloat16_as_ushort(hz) | ((uint32_t)__bfloat16_as_ushort(hw) << 16);
    L.x = (uint32_t)__bfloat16_as_ushort(lx) | ((uint32_t)__bfloat16_as_ushort(ly) << 16);
    L.y = (uint32_t)__bfloat16_as_ushort(lz) | ((uint32_t)__bfloat16_as_ushort(lw) << 16);
}

// -------- KNN: warp per query, lane-sorted distributed top-32 (R8 design) --------
__global__ __launch_bounds__(1024) void knn_kernel(const float* __restrict__ xyz,
                           const int*   __restrict__ sidx,
                           float*       __restrict__ out_xyz) {
    extern __shared__ float4 pts[];
    const int tid  = threadIdx.x;
    const int warp = tid >> 5, lane = tid & 31;
    const int qbase = blockIdx.x * 32;
    const int b = qbase / P2;
    const float* bx = xyz + (size_t)b * P1 * 3;

    for (int j = tid; j < P1; j += 1024) {
        float x = bx[3*j], y = bx[3*j+1], z = bx[3*j+2];
        float r2 = __fadd_rn(__fadd_rn(__fmul_rn(x,x), __fmul_rn(y,y)), __fmul_rn(z,z));
        pts[j] = make_float4(x, y, z, r2);
    }
    __syncthreads();

    const int q  = qbase + warp;
    const int si = sidx[q];
    const float qx = bx[3*si], qy = bx[3*si+1], qz = bx[3*si+2];
    const float rA = __fadd_rn(__fadd_rn(__fmul_rn(qx,qx), __fmul_rn(qy,qy)), __fmul_rn(qz,qz));
    if (lane < 3) out_xyz[(size_t)q*3 + lane] = (lane == 0) ? qx : (lane == 1 ? qy : qz);

    float best_d = FLT_MAX; int best_i = 0;
    float thr = FLT_MAX;

    for (int j0 = 0; j0 < P1; j0 += 32) {
        float4 pt = pts[j0 + lane];
        float dot = __fmaf_rn(qz, pt.z, __fmaf_rn(qy, pt.y, __fmul_rn(qx, pt.x)));
        float d   = __fadd_rn(__fsub_rn(rA, __fmul_rn(2.f, dot)), pt.w);
        unsigned m = __ballot_sync(0xffffffffu, d < thr);
        while (m) {
            int src = __ffs(m) - 1; m &= m - 1;
            float dc = __shfl_sync(0xffffffffu, d, src);
            unsigned bal = __ballot_sync(0xffffffffu, dc < best_d);
            if (bal) {
                int pos  = __ffs(bal) - 1;
                float ud = __shfl_up_sync(0xffffffffu, best_d, 1);
                int   ui = __shfl_up_sync(0xffffffffu, best_i, 1);
                if (lane > pos)       { best_d = ud; best_i = ui; }
                else if (lane == pos) { best_d = dc; best_i = j0 + src; }
            }
        }
        thr = __shfl_sync(0xffffffffu, best_d, 31);
    }
    g_nn[(size_t)q*KNB + lane] = best_i;
}

// -------- GEMM layer via mma.sync bf16 (3-term split), M=128/CTA, 2 CTAs/SM --------
template<int KPAD, int CIN, int N, int MODE, int POOL>
__global__ __launch_bounds__(256, 2) void gemm_kernel(
        const float* __restrict__ feat, const float* __restrict__ xyz,
        const float* __restrict__ qxyz, const float* __restrict__ y_in,
        const float* __restrict__ W,    float* __restrict__ y_out, int prev)
{
    extern __shared__ char smem[];
    constexpr int ST = KPAD + 8;
    constexpr int OFF_AH = 0;
    constexpr int OFF_AL = 128*ST*2;
    constexpr int OFF_BH = 2*OFF_AL;
    constexpr int OFF_BL = OFF_BH + N*ST*2;
    constexpr int OFF_S  = OFF_BL + N*ST*2;
    float* ssum = (float*)(smem + OFF_S);
    float* ssq  = ssum + N;
    const uint32_t sb = smem_u32(smem);
    const int tid = threadIdx.x;
    const int n0  = blockIdx.x * 128;
    const int cq  = tid & 15, rs = tid >> 4;

    if (tid < N) { ssum[tid] = 0.f; ssq[tid] = 0.f; }

    if (MODE == 0) {
        uint4 z = make_uint4(0,0,0,0);
        if (tid < 128 + N) {
            int isA = tid < 128;
            int row = isA ? tid : tid - 128;
            char* base = smem + (isA ? OFF_AH : OFF_BH) + row*ST*2 + 128;
            char* basl = smem + (isA ? OFF_AL : OFF_BL) + row*ST*2 + 128;
            *(uint4*)(base) = z;      *(uint4*)(base + 16) = z;
            *(uint4*)(basl) = z;      *(uint4*)(basl + 16) = z;
        }
        #pragma unroll
        for (int it = 0; it < 8; it++) {
            int row = rs + 16*it;
            int n   = n0 + row;
            int b   = n >> 16;
            int nn  = g_nn[n];
            float4 f = *(const float4*)(feat + (size_t)(b*P1 + nn)*64 + 4*cq);
            uint2 H, L; split4(f, H, L);
            *(uint2*)(smem + OFF_AH + row*ST*2 + 8*cq) = H;
            *(uint2*)(smem + OFF_AL + row*ST*2 + 8*cq) = L;
            if (cq == 0) {
                int q = n >> 5;
                const float* nx = xyz  + (size_t)(b*P1 + nn)*3;
                const float* qp = qxyz + (size_t)q*3;
                #pragma unroll
                for (int j = 0; j < 3; j++) {
                    __nv_bfloat16 h, l; split1(__fsub_rn(nx[j], qp[j]), h, l);
                    *(__nv_bfloat16*)(smem + OFF_AH + row*ST*2 + 128 + 2*j) = h;
                    *(__nv_bfloat16*)(smem + OFF_AL + row*ST*2 + 128 + 2*j) = l;
                }
            }
        }
        #pragma unroll
        for (int it = 0; it < N/16; it++) {
            int o = rs + 16*it;
            const float* wr = W + (size_t)o*CIN;
            float4 w4 = make_float4(wr[4*cq], wr[4*cq+1], wr[4*cq+2], wr[4*cq+3]);
            uint2 H, L; split4(w4, H, L);
            *(uint2*)(smem + OFF_BH + o*ST*2 + 8*cq) = H;
            *(uint2*)(smem + OFF_BL + o*ST*2 + 8*cq) = L;
            if (cq == 0) {
                #pragma unroll
                for (int j = 0; j < 3; j++) {
                    __nv_bfloat16 h, l; split1(wr[64 + j], h, l);
                    *(__nv_bfloat16*)(smem + OFF_BH + o*ST*2 + 128 + 2*j) = h;
                    *(__nv_bfloat16*)(smem + OFF_BL + o*ST*2 + 128 + 2*j) = l;
                }
            }
        }
    } else {
        const float4 sc4 = *(const float4*)(g_scale[prev] + 4*cq);
        const float4 sh4 = *(const float4*)(g_shift[prev] + 4*cq);
        #pragma unroll
        for (int it = 0; it < 8; it++) {
            int row = rs + 16*it;
            float4 v = *(const float4*)(y_in + (size_t)(n0 + row)*64 + 4*cq);
            v.x = fmaxf(__fmaf_rn(sc4.x, v.x, sh4.x), 0.f);
            v.y = fmaxf(__fmaf_rn(sc4.y, v.y, sh4.y), 0.f);
            v.z = fmaxf(__fmaf_rn(sc4.z, v.z, sh4.z), 0.f);
            v.w = fmaxf(__fmaf_rn(sc4.w, v.w, sh4.w), 0.f);
            uint2 H, L; split4(v, H, L);
            *(uint2*)(smem + OFF_AH + row*ST*2 + 8*cq) = H;
            *(uint2*)(smem + OFF_AL + row*ST*2 + 8*cq) = L;
        }
        #pragma unroll
        for (int it = 0; it < N/16; it++) {
            int o = rs + 16*it;
            float4 w4 = *(const float4*)(W + (size_t)o*64 + 4*cq);
            uint2 H, L; split4(w4, H, L);
            *(uint2*)(smem + OFF_BH + o*ST*2 + 8*cq) = H;
            *(uint2*)(smem + OFF_BL + o*ST*2 + 8*cq) = L;
        }
    }
    __syncthreads();

    const int w = tid >> 5, lane = tid & 31;
    const int mw = w & 3, nw = w >> 2;
    constexpr int NB = N/16;

    float acc[2][NB][4];
    #pragma unroll
    for (int mh = 0; mh < 2; mh++)
        #pragma unroll
        for (int nb = 0; nb < NB; nb++)
            #pragma unroll
            for (int j = 0; j < 4; j++) acc[mh][nb][j] = 0.f;

    const uint32_t aoff = ((mw*32 + (lane & 15))*ST + (lane >> 4)*8) * 2;
    // ldsm4 for b: matrices = [nb, k0], [nb, k1], [nb+1, k0], [nb+1, k1]
    const uint32_t boff4 = ((nw*(N/2) + (lane & 7) + ((lane >> 4) * 8))*ST + ((lane >> 3) & 1)*8) * 2;

    #pragma unroll
    for (int kk = 0; kk < KPAD/16; kk++) {
        uint32_t ah[2][4], al[2][4];
        #pragma unroll
        for (int mh = 0; mh < 2; mh++) {
            ldsm4(ah[mh], sb + OFF_AH + aoff + (mh*16*ST + kk*16)*2);
            ldsm4(al[mh], sb + OFF_AL + aoff + (mh*16*ST + kk*16)*2);
        }
        #pragma unroll
        for (int nbp = 0; nbp < NB/2; nbp++) {
            uint32_t bh[4], bl[4];
            ldsm4(bh, sb + OFF_BH + boff4 + (nbp*16*ST + kk*16)*2);
            ldsm4(bl, sb + OFF_BL + boff4 + (nbp*16*ST + kk*16)*2);
            #pragma unroll
            for (int j = 0; j < 2; j++) {
                #pragma unroll
                for (int mh = 0; mh < 2; mh++) {
                    mma16816(acc[mh][2*nbp+j], ah[mh], bh + 2*j);
                    mma16816(acc[mh][2*nbp+j], ah[mh], bl + 2*j);
                    mma16816(acc[mh][2*nbp+j], al[mh], bh + 2*j);
                }
            }
        }
    }

    const int g = lane >> 2, t = lane & 3;
    #pragma unroll
    for (int nb = 0; nb < NB; nb++) {
        float s0 = acc[0][nb][0] + acc[0][nb][2] + acc[1][nb][0] + acc[1][nb][2];
        float s1 = acc[0][nb][1] + acc[0][nb][3] + acc[1][nb][1] + acc[1][nb][3];
        float q0 = acc[0][nb][0]*acc[0][nb][0] + acc[0][nb][2]*acc[0][nb][2]
                 + acc[1][nb][0]*acc[1][nb][0] + acc[1][nb][2]*acc[1][nb][2];
        float q1 = acc[0][nb][1]*acc[0][nb][1] + acc[0][nb][3]*acc[0][nb][3]
                 + acc[1][nb][1]*acc[1][nb][1] + acc[1][nb][3]*acc[1][nb][3];
        float mx0, mn0, mx1, mn1;
        if (POOL) {
            mx0 = fmaxf(fmaxf(acc[0][nb][0], acc[0][nb][2]), fmaxf(acc[1][nb][0], acc[1][nb][2]));
            mn0 = fminf(fminf(acc[0][nb][0], acc[0][nb][2]), fminf(acc[1][nb][0], acc[1][nb][2]));
            mx1 = fmaxf(fmaxf(acc[0][nb][1], acc[0][nb][3]), fmaxf(acc[1][nb][1], acc[1][nb][3]));
            mn1 = fminf(fminf(acc[0][nb][1], acc[0][nb][3]), fminf(acc[1][nb][1], acc[1][nb][3]));
        }
        #pragma unroll
        for (int off = 4; off < 32; off <<= 1) {
            s0 += __shfl_xor_sync(0xffffffffu, s0, off);
            s1 += __shfl_xor_sync(0xffffffffu, s1, off);
            q0 += __shfl_xor_sync(0xffffffffu, q0, off);
            q1 += __shfl_xor_sync(0xffffffffu, q1, off);
            if (POOL) {
                mx0 = fmaxf(mx0, __shfl_xor_sync(0xffffffffu, mx0, off));
                mn0 = fminf(mn0, __shfl_xor_sync(0xffffffffu, mn0, off));
                mx1 = fmaxf(mx1, __shfl_xor_sync(0xffffffffu, mx1, off));
                mn1 = fminf(mn1, __shfl_xor_sync(0xffffffffu, mn1, off));
            }
        }
        if (g == 0) {
            int col = nw*(N/2) + nb*8 + 2*t;
            atomicAdd(&ssum[col],   s0); atomicAdd(&ssum[col+1], s1);
            atomicAdd(&ssq[col],    q0); atomicAdd(&ssq[col+1],  q1);
            if (POOL) {
                int q = blockIdx.x*4 + mw;
                g_mx[(size_t)q*128 + col]   = mx0;  g_mn[(size_t)q*128 + col]   = mn0;
                g_mx[(size_t)q*128 + col+1] = mx1;  g_mn[(size_t)q*128 + col+1] = mn1;
            }
        }
    }

    if (!POOL) {
        #pragma unroll
        for (int mh = 0; mh < 2; mh++) {
            #pragma unroll
            for (int nb = 0; nb < NB; nb++) {
                int row = n0 + mw*32 + mh*16 + g;
                int col = nw*(N/2) + nb*8 + 2*t;
                *(float2*)(y_out + (size_t)row*N + col)       = make_float2(acc[mh][nb][0], acc[mh][nb][1]);
                *(float2*)(y_out + (size_t)(row + 8)*N + col) = make_float2(acc[mh][nb][2], acc[mh][nb][3]);
            }
        }
    }

    __syncthreads();
    if (tid < N) {
        atomicAdd(&g_sum[tid],   (double)ssum[tid]);
        atomicAdd(&g_sqsum[tid], (double)ssq[tid]);
    }
}

// -------- BN finalize --------
__global__ void finalize_kernel(const float* __restrict__ gamma,
                                const float* __restrict__ beta,
                                int layer) {
    int o = threadIdx.x;
    double mean = g_sum[o]   * (1.0 / (double)NTOT);
    double var  = g_sqsum[o] * (1.0 / (double)NTOT) - mean*mean;
    float sc = gamma[o] * (float)(1.0 / sqrt(var + 1e-5));
    g_scale[layer][o] = sc;
    g_shift[layer][o] = __fmaf_rn(-(float)mean, sc, beta[o]);
    g_sum[o] = 0.0; g_sqsum[o] = 0.0;
}

// -------- final affine+relu on pooled max/min --------
__global__ void pool_apply_kernel(float* __restrict__ out) {
    int idx = blockIdx.x * 256 + threadIdx.x;
    int o = idx & 127;
    float sc = g_scale[2][o], sh = g_shift[2][o];
    float vmx = __fmaf_rn(sc, g_mx[idx], sh);
    float vmn = __fmaf_rn(sc, g_mn[idx], sh);
    out[idx] = fmaxf(fmaxf(vmx, vmn), 0.f);
}

extern "C" void kernel_launch(void* const* d_in, const int* in_sizes, int n_in,
                              void* d_out, int out_size) {
    const float* xyz  = (const float*)d_in[0];
    const float* feat = (const float*)d_in[1];
    const int*   sidx = (const int*)d_in[2];
    const float *w1=(const float*)d_in[3],
                *g1=(const float*)d_in[5],  *t1=(const float*)d_in[6];
    const float *w2=(const float*)d_in[7],
                *g2=(const float*)d_in[9],  *t2=(const float*)d_in[10];
    const float *w3=(const float*)d_in[11],
                *g3=(const float*)d_in[13], *t3=(const float*)d_in[14];
    float* out      = (float*)d_out;
    float* new_xyz  = out;
    float* new_feat = out + NQ*3;

    float* bufA; cudaGetSymbolAddress((void**)&bufA, g_bufA);
    float* bufB; cudaGetSymbolAddress((void**)&bufB, g_bufB);

    const int S1 = (256 + 128) * (80+8) * 2 + 64*8;    // 68096
    const int S2 = (256 + 128) * (64+8) * 2 + 64*8;    // 55808
    const int S3 = (256 + 256) * (64+8) * 2 + 128*8;   // 74752
    cudaFuncSetAttribute(knn_kernel, cudaFuncAttributeMaxDynamicSharedMemorySize, 131072);
    cudaFuncSetAttribute(gemm_kernel<80,67,64,0,0>,  cudaFuncAttributeMaxDynamicSharedMemorySize, S1);
    cudaFuncSetAttribute(gemm_kernel<64,64,64,1,0>,  cudaFuncAttributeMaxDynamicSharedMemorySize, S2);
    cudaFuncSetAttribute(gemm_kernel<64,64,128,1,1>, cudaFuncAttributeMaxDynamicSharedMemorySize, S3);

    knn_kernel<<<NQ/32, 1024, 131072>>>(xyz, sidx, new_xyz);
    gemm_kernel<80,67,64,0,0><<<NTOT/128, 256, S1>>>(feat, xyz, new_xyz, nullptr, w1, bufA, 0);
    finalize_kernel<<<1,64>>>(g1, t1, 0);
    gemm_kernel<64,64,64,1,0><<<NTOT/128, 256, S2>>>(nullptr, nullptr, nullptr, bufA, w2, bufB, 0);
    finalize_kernel<<<1,64>>>(g2, t2, 1);
    gemm_kernel<64,64,128,1,1><<<NTOT/128, 256, S3>>>(nullptr, nullptr, nullptr, bufB, w3, nullptr, 1);
    finalize_kernel<<<1,128>>>(g3, t3, 2);
    pool_apply_kernel<<<(NQ*128)/256, 256>>>(new_feat);
}

// round 11
// speedup vs baseline: 1.4216x; 1.0643x over previous
#include <cuda_runtime.h>
#include <cuda_bf16.h>
#include <cfloat>
#include <math.h>
#include <cstdint>

#define BSZ 8
#define P1  8192
#define P2  2048
#define KNB 32
#define NQ  16384
#define NTOT 524288ull

typedef unsigned long long ull;

__device__ int    g_nn[NQ*KNB];
__device__ float  g_bufA[NTOT*64];    // y1 [n][64]
__device__ float  g_bufB[NTOT*64];    // y2 [n][64]
__device__ float  g_mx[NQ*128];
__device__ float  g_mn[NQ*128];
__device__ double g_sum[128];
__device__ double g_sqsum[128];
__device__ float  g_scale[3][128];
__device__ float  g_shift[3][128];

static __device__ __forceinline__ uint32_t smem_u32(const void* p) {
    uint32_t a; asm("{ .reg .u64 t; cvta.to.shared.u64 t, %1; cvt.u32.u64 %0, t; }" : "=r"(a) : "l"(p));
    return a;
}
static __device__ __forceinline__ void ldsm4(uint32_t* r, uint32_t a) {
    asm volatile("ldmatrix.sync.aligned.m8n8.x4.shared.b16 {%0,%1,%2,%3}, [%4];"
        : "=r"(r[0]), "=r"(r[1]), "=r"(r[2]), "=r"(r[3]) : "r"(a));
}
static __device__ __forceinline__ void ldsm2(uint32_t* r, uint32_t a) {
    asm volatile("ldmatrix.sync.aligned.m8n8.x2.shared.b16 {%0,%1}, [%2];"
        : "=r"(r[0]), "=r"(r[1]) : "r"(a));
}
static __device__ __forceinline__ void mma16816(float* d, const uint32_t* a, const uint32_t* b) {
    asm volatile("mma.sync.aligned.m16n8k16.row.col.f32.bf16.bf16.f32 "
        "{%0,%1,%2,%3},{%4,%5,%6,%7},{%8,%9},{%0,%1,%2,%3};"
        : "+f"(d[0]), "+f"(d[1]), "+f"(d[2]), "+f"(d[3])
        : "r"(a[0]), "r"(a[1]), "r"(a[2]), "r"(a[3]), "r"(b[0]), "r"(b[1]));
}
static __device__ __forceinline__ void split1(float v, __nv_bfloat16 &h, __nv_bfloat16 &l) {
    h = __float2bfloat16_rn(v);
    l = __float2bfloat16_rn(v - __bfloat162float(h));
}
static __device__ __forceinline__ void split4(float4 v, uint2 &H, uint2 &L) {
    __nv_bfloat16 hx, hy, hz, hw, lx, ly, lz, lw;
    split1(v.x, hx, lx); split1(v.y, hy, ly);
    split1(v.z, hz, lz); split1(v.w, hw, lw);
    H.x = (uint32_t)__bfloat16_as_ushort(hx) | ((uint32_t)__bfloat16_as_ushort(hy) << 16);
    H.y = (uint32_t)__bfloat16_as_ushort(hz) | ((uint32_t)__bfloat16_as_ushort(hw) << 16);
    L.x = (uint32_t)__bfloat16_as_ushort(lx) | ((uint32_t)__bfloat16_as_ushort(ly) << 16);
    L.y = (uint32_t)__bfloat16_as_ushort(lz) | ((uint32_t)__bfloat16_as_ushort(lw) << 16);
}

// -------- KNN: warp per query, lane-sorted distributed top-32 (R8 design + block offset) --------
__global__ __launch_bounds__(1024) void knn_kernel(const float* __restrict__ xyz,
                           const int*   __restrict__ sidx,
                           float*       __restrict__ out_xyz, int qoff) {
    extern __shared__ float4 pts[];
    const int tid  = threadIdx.x;
    const int warp = tid >> 5, lane = tid & 31;
    const int qbase = (blockIdx.x + qoff) * 32;
    const int b = qbase / P2;
    const float* bx = xyz + (size_t)b * P1 * 3;

    for (int j = tid; j < P1; j += 1024) {
        float x = bx[3*j], y = bx[3*j+1], z = bx[3*j+2];
        float r2 = __fadd_rn(__fadd_rn(__fmul_rn(x,x), __fmul_rn(y,y)), __fmul_rn(z,z));
        pts[j] = make_float4(x, y, z, r2);
    }
    __syncthreads();

    const int q  = qbase + warp;
    const int si = sidx[q];
    const float qx = bx[3*si], qy = bx[3*si+1], qz = bx[3*si+2];
    const float rA = __fadd_rn(__fadd_rn(__fmul_rn(qx,qx), __fmul_rn(qy,qy)), __fmul_rn(qz,qz));
    if (lane < 3) out_xyz[(size_t)q*3 + lane] = (lane == 0) ? qx : (lane == 1 ? qy : qz);

    float best_d = FLT_MAX; int best_i = 0;
    float thr = FLT_MAX;

    for (int j0 = 0; j0 < P1; j0 += 32) {
        float4 pt = pts[j0 + lane];
        float dot = __fmaf_rn(qz, pt.z, __fmaf_rn(qy, pt.y, __fmul_rn(qx, pt.x)));
        float d   = __fadd_rn(__fsub_rn(rA, __fmul_rn(2.f, dot)), pt.w);
        unsigned m = __ballot_sync(0xffffffffu, d < thr);
        while (m) {
            int src = __ffs(m) - 1; m &= m - 1;
            float dc = __shfl_sync(0xffffffffu, d, src);
            unsigned bal = __ballot_sync(0xffffffffu, dc < best_d);
            if (bal) {
                int pos  = __ffs(bal) - 1;
                float ud = __shfl_up_sync(0xffffffffu, best_d, 1);
                int   ui = __shfl_up_sync(0xffffffffu, best_i, 1);
                if (lane > pos)       { best_d = ud; best_i = ui; }
                else if (lane == pos) { best_d = dc; best_i = j0 + src; }
            }
        }
        thr = __shfl_sync(0xffffffffu, best_d, 31);
    }
    g_nn[(size_t)q*KNB + lane] = best_i;
}

// -------- GEMM layer via mma.sync bf16 (3-term split), M=128/CTA (exact R8 body + boff) --------
template<int KPAD, int CIN, int N, int MODE, int POOL>
__global__ __launch_bounds__(256) void gemm_kernel(
        const float* __restrict__ feat, const float* __restrict__ xyz,
        const float* __restrict__ qxyz, const float* __restrict__ y_in,
        const float* __restrict__ W,    float* __restrict__ y_out, int prev, int boff)
{
    extern __shared__ char smem[];
    constexpr int ST = KPAD + 8;
    constexpr int OFF_AH = 0;
    constexpr int OFF_AL = 128*ST*2;
    constexpr int OFF_BH = 2*OFF_AL;
    constexpr int OFF_BL = OFF_BH + N*ST*2;
    constexpr int OFF_S  = OFF_BL + N*ST*2;
    float* ssum = (float*)(smem + OFF_S);
    float* ssq  = ssum + N;
    const uint32_t sb = smem_u32(smem);
    const int tid = threadIdx.x;
    const int n0  = (blockIdx.x + boff) * 128;
    const int cq  = tid & 15, rs = tid >> 4;

    if (tid < N) { ssum[tid] = 0.f; ssq[tid] = 0.f; }

    if (MODE == 0) {
        uint4 z = make_uint4(0,0,0,0);
        if (tid < 128 + N) {
            int isA = tid < 128;
            int row = isA ? tid : tid - 128;
            char* base = smem + (isA ? OFF_AH : OFF_BH) + row*ST*2 + 128;
            char* basl = smem + (isA ? OFF_AL : OFF_BL) + row*ST*2 + 128;
            *(uint4*)(base) = z;      *(uint4*)(base + 16) = z;
            *(uint4*)(basl) = z;      *(uint4*)(basl + 16) = z;
        }
        #pragma unroll
        for (int it = 0; it < 8; it++) {
            int row = rs + 16*it;
            int n   = n0 + row;
            int b   = n >> 16;
            int nn  = g_nn[n];
            float4 f = *(const float4*)(feat + (size_t)(b*P1 + nn)*64 + 4*cq);
            uint2 H, L; split4(f, H, L);
            *(uint2*)(smem + OFF_AH + row*ST*2 + 8*cq) = H;
            *(uint2*)(smem + OFF_AL + row*ST*2 + 8*cq) = L;
            if (cq == 0) {
                int q = n >> 5;
                const float* nx = xyz  + (size_t)(b*P1 + nn)*3;
                const float* qp = qxyz + (size_t)q*3;
                #pragma unroll
                for (int j = 0; j < 3; j++) {
                    __nv_bfloat16 h, l; split1(__fsub_rn(nx[j], qp[j]), h, l);
                    *(__nv_bfloat16*)(smem + OFF_AH + row*ST*2 + 128 + 2*j) = h;
                    *(__nv_bfloat16*)(smem + OFF_AL + row*ST*2 + 128 + 2*j) = l;
                }
            }
        }
        #pragma unroll
        for (int it = 0; it < N/16; it++) {
            int o = rs + 16*it;
            const float* wr = W + (size_t)o*CIN;
            float4 w4 = make_float4(wr[4*cq], wr[4*cq+1], wr[4*cq+2], wr[4*cq+3]);
            uint2 H, L; split4(w4, H, L);
            *(uint2*)(smem + OFF_BH + o*ST*2 + 8*cq) = H;
            *(uint2*)(smem + OFF_BL + o*ST*2 + 8*cq) = L;
            if (cq == 0) {
                #pragma unroll
                for (int j = 0; j < 3; j++) {
                    __nv_bfloat16 h, l; split1(wr[64 + j], h, l);
                    *(__nv_bfloat16*)(smem + OFF_BH + o*ST*2 + 128 + 2*j) = h;
                    *(__nv_bfloat16*)(smem + OFF_BL + o*ST*2 + 128 + 2*j) = l;
                }
            }
        }
    } else {
        const float4 sc4 = *(const float4*)(g_scale[prev] + 4*cq);
        const float4 sh4 = *(const float4*)(g_shift[prev] + 4*cq);
        #pragma unroll
        for (int it = 0; it < 8; it++) {
            int row = rs + 16*it;
            float4 v = *(const float4*)(y_in + (size_t)(n0 + row)*64 + 4*cq);
            v.x = fmaxf(__fmaf_rn(sc4.x, v.x, sh4.x), 0.f);
            v.y = fmaxf(__fmaf_rn(sc4.y, v.y, sh4.y), 0.f);
            v.z = fmaxf(__fmaf_rn(sc4.z, v.z, sh4.z), 0.f);
            v.w = fmaxf(__fmaf_rn(sc4.w, v.w, sh4.w), 0.f);
            uint2 H, L; split4(v, H, L);
            *(uint2*)(smem + OFF_AH + row*ST*2 + 8*cq) = H;
            *(uint2*)(smem + OFF_AL + row*ST*2 + 8*cq) = L;
        }
        #pragma unroll
        for (int it = 0; it < N/16; it++) {
            int o = rs + 16*it;
            float4 w4 = *(const float4*)(W + (size_t)o*64 + 4*cq);
            uint2 H, L; split4(w4, H, L);
            *(uint2*)(smem + OFF_BH + o*ST*2 + 8*cq) = H;
            *(uint2*)(smem + OFF_BL + o*ST*2 + 8*cq) = L;
        }
    }
    __syncthreads();

    const int w = tid >> 5, lane = tid & 31;
    const int mw = w & 3, nw = w >> 2;
    constexpr int NB = N/16;

    float acc[2][NB][4];
    #pragma unroll
    for (int mh = 0; mh < 2; mh++)
        #pragma unroll
        for (int nb = 0; nb < NB; nb++)
            #pragma unroll
            for (int j = 0; j < 4; j++) acc[mh][nb][j] = 0.f;

    const uint32_t aoff = ((mw*32 + (lane & 15))*ST + (lane >> 4)*8) * 2;
    const uint32_t boff2 = ((nw*(N/2) + (lane & 7))*ST + ((lane >> 3) & 1)*8) * 2;

    #pragma unroll
    for (int kk = 0; kk < KPAD/16; kk++) {
        uint32_t ah[2][4], al[2][4];
        #pragma unroll
        for (int mh = 0; mh < 2; mh++) {
            ldsm4(ah[mh], sb + OFF_AH + aoff + (mh*16*ST + kk*16)*2);
            ldsm4(al[mh], sb + OFF_AL + aoff + (mh*16*ST + kk*16)*2);
        }
        #pragma unroll
        for (int nb = 0; nb < NB; nb++) {
            uint32_t bh[2], bl[2];
            ldsm2(bh, sb + OFF_BH + boff2 + (nb*8*ST + kk*16)*2);
            ldsm2(bl, sb + OFF_BL + boff2 + (nb*8*ST + kk*16)*2);
            #pragma unroll
            for (int mh = 0; mh < 2; mh++) {
                mma16816(acc[mh][nb], ah[mh], bh);
                mma16816(acc[mh][nb], ah[mh], bl);
                mma16816(acc[mh][nb], al[mh], bh);
            }
        }
    }

    const int g = lane >> 2, t = lane & 3;
    #pragma unroll
    for (int nb = 0; nb < NB; nb++) {
        float s0 = acc[0][nb][0] + acc[0][nb][2] + acc[1][nb][0] + acc[1][nb][2];
        float s1 = acc[0][nb][1] + acc[0][nb][3] + acc[1][nb][1] + acc[1][nb][3];
        float q0 = acc[0][nb][0]*acc[0][nb][0] + acc[0][nb][2]*acc[0][nb][2]
                 + acc[1][nb][0]*acc[1][nb][0] + acc[1][nb][2]*acc[1][nb][2];
        float q1 = acc[0][nb][1]*acc[0][nb][1] + acc[0][nb][3]*acc[0][nb][3]
                 + acc[1][nb][1]*acc[1][nb][1] + acc[1][nb][3]*acc[1][nb][3];
        float mx0, mn0, mx1, mn1;
        if (POOL) {
            mx0 = fmaxf(fmaxf(acc[0][nb][0], acc[0][nb][2]), fmaxf(acc[1][nb][0], acc[1][nb][2]));
            mn0 = fminf(fminf(acc[0][nb][0], acc[0][nb][2]), fminf(acc[1][nb][0], acc[1][nb][2]));
            mx1 = fmaxf(fmaxf(acc[0][nb][1], acc[0][nb][3]), fmaxf(acc[1][nb][1], acc[1][nb][3]));
            mn1 = fminf(fminf(acc[0][nb][1], acc[0][nb][3]), fminf(acc[1][nb][1], acc[1][nb][3]));
        }
        #pragma unroll
        for (int off = 4; off < 32; off <<= 1) {
            s0 += __shfl_xor_sync(0xffffffffu, s0, off);
            s1 += __shfl_xor_sync(0xffffffffu, s1, off);
            q0 += __shfl_xor_sync(0xffffffffu, q0, off);
            q1 += __shfl_xor_sync(0xffffffffu, q1, off);
            if (POOL) {
                mx0 = fmaxf(mx0, __shfl_xor_sync(0xffffffffu, mx0, off));
                mn0 = fminf(mn0, __shfl_xor_sync(0xffffffffu, mn0, off));
                mx1 = fmaxf(mx1, __shfl_xor_sync(0xffffffffu, mx1, off));
                mn1 = fminf(mn1, __shfl_xor_sync(0xffffffffu, mn1, off));
            }
        }
        if (g == 0) {
            int col = nw*(N/2) + nb*8 + 2*t;
            atomicAdd(&ssum[col],   s0); atomicAdd(&ssum[col+1], s1);
            atomicAdd(&ssq[col],    q0); atomicAdd(&ssq[col+1],  q1);
            if (POOL) {
                int q = (n0 >> 5) + mw;
                g_mx[(size_t)q*128 + col]   = mx0;  g_mn[(size_t)q*128 + col]   = mn0;
                g_mx[(size_t)q*128 + col+1] = mx1;  g_mn[(size_t)q*128 + col+1] = mn1;
            }
        }
    }

    if (!POOL) {
        #pragma unroll
        for (int mh = 0; mh < 2; mh++) {
            #pragma unroll
            for (int nb = 0; nb < NB; nb++) {
                int row = n0 + mw*32 + mh*16 + g;
                int col = nw*(N/2) + nb*8 + 2*t;
                *(float2*)(y_out + (size_t)row*N + col)       = make_float2(acc[mh][nb][0], acc[mh][nb][1]);
                *(float2*)(y_out + (size_t)(row + 8)*N + col) = make_float2(acc[mh][nb][2], acc[mh][nb][3]);
            }
        }
    }

    __syncthreads();
    if (tid < N) {
        atomicAdd(&g_sum[tid],   (double)ssum[tid]);
        atomicAdd(&g_sqsum[tid], (double)ssq[tid]);
    }
}

// -------- BN finalize --------
__global__ void finalize_kernel(const float* __restrict__ gamma,
                                const float* __restrict__ beta,
                                int layer) {
    int o = threadIdx.x;
    double mean = g_sum[o]   * (1.0 / (double)NTOT);
    double var  = g_sqsum[o] * (1.0 / (double)NTOT) - mean*mean;
    float sc = gamma[o] * (float)(1.0 / sqrt(var + 1e-5));
    g_scale[layer][o] = sc;
    g_shift[layer][o] = __fmaf_rn(-(float)mean, sc, beta[o]);
    g_sum[o] = 0.0; g_sqsum[o] = 0.0;
}

// -------- final affine+relu on pooled max/min --------
__global__ void pool_apply_kernel(float* __restrict__ out) {
    int idx = blockIdx.x * 256 + threadIdx.x;
    int o = idx & 127;
    float sc = g_scale[2][o], sh = g_shift[2][o];
    float vmx = __fmaf_rn(sc, g_mx[idx], sh);
    float vmn = __fmaf_rn(sc, g_mn[idx], sh);
    out[idx] = fmaxf(fmaxf(vmx, vmn), 0.f);
}

extern "C" void kernel_launch(void* const* d_in, const int* in_sizes, int n_in,
                              void* d_out, int out_size) {
    const float* xyz  = (const float*)d_in[0];
    const float* feat = (const float*)d_in[1];
    const int*   sidx = (const int*)d_in[2];
    const float *w1=(const float*)d_in[3],
                *g1=(const float*)d_in[5],  *t1=(const float*)d_in[6];
    const float *w2=(const float*)d_in[7],
                *g2=(const float*)d_in[9],  *t2=(const float*)d_in[10];
    const float *w3=(const float*)d_in[11],
                *g3=(const float*)d_in[13], *t3=(const float*)d_in[14];
    float* out      = (float*)d_out;
    float* new_xyz  = out;
    float* new_feat = out + NQ*3;

    float* bufA; cudaGetSymbolAddress((void**)&bufA, g_bufA);
    float* bufB; cudaGetSymbolAddress((void**)&bufB, g_bufB);

    const int S1 = (256 + 128) * (80+8) * 2 + 64*8;    // 68096
    const int S2 = (256 + 128) * (64+8) * 2 + 64*8;    // 55808
    const int S3 = (256 + 256) * (64+8) * 2 + 128*8;   // 74752
    cudaFuncSetAttribute(knn_kernel, cudaFuncAttributeMaxDynamicSharedMemorySize, 131072);
    cudaFuncSetAttribute(gemm_kernel<80,67,64,0,0>,  cudaFuncAttributeMaxDynamicSharedMemorySize, S1);
    cudaFuncSetAttribute(gemm_kernel<64,64,64,1,0>,  cudaFuncAttributeMaxDynamicSharedMemorySize, S2);
    cudaFuncSetAttribute(gemm_kernel<64,64,128,1,1>, cudaFuncAttributeMaxDynamicSharedMemorySize, S3);

    // fork-join: knn_A -> (gemm1_A on s1) || (knn_B -> gemm1_B on s0); join before finalize1
    cudaStream_t s1;
    cudaStreamCreateWithFlags(&s1, cudaStreamNonBlocking);   // host resource; not device memory
    cudaEvent_t e0, e1;
    cudaEventCreateWithFlags(&e0, cudaEventDisableTiming);
    cudaEventCreateWithFlags(&e1, cudaEventDisableTiming);

    knn_kernel<<<256, 1024, 131072>>>(xyz, sidx, new_xyz, 0);      // batches 0..3
    cudaEventRecord(e0, 0);
    cudaStreamWaitEvent(s1, e0, 0);
    gemm_kernel<80,67,64,0,0><<<2048, 256, S1, s1>>>(feat, xyz, new_xyz, nullptr, w1, bufA, 0, 0);
    cudaEventRecord(e1, s1);

    knn_kernel<<<256, 1024, 131072>>>(xyz, sidx, new_xyz, 256);    // batches 4..7
    gemm_kernel<80,67,64,0,0><<<2048, 256, S1>>>(feat, xyz, new_xyz, nullptr, w1, bufA, 0, 2048);
    cudaStreamWaitEvent(0, e1, 0);                                  // join before finalize

    finalize_kernel<<<1,64>>>(g1, t1, 0);
    gemm_kernel<64,64,64,1,0><<<NTOT/128, 256, S2>>>(nullptr, nullptr, nullptr, bufA, w2, bufB, 0, 0);
    finalize_kernel<<<1,64>>>(g2, t2, 1);
    gemm_kernel<64,64,128,1,1><<<NTOT/128, 256, S3>>>(nullptr, nullptr, nullptr, bufB, w3, nullptr, 1, 0);
    finalize_kernel<<<1,128>>>(g3, t3, 2);
    pool_apply_kernel<<<(NQ*128)/256, 256>>>(new_feat);
}